// round 17
// baseline (speedup 1.0000x reference)
#include <cuda_runtime.h>
#include <math.h>
#include <mma.h>

using namespace nvcuda;

#define S_    32
#define N_    128
#define NM1   127
#define D_    256
#define F_    516
#define TRI_  8128
#define M4    (S_*NM1)      // 4064
#define EDGES (S_*TRI_)     // 260096
#define NBATCH (EDGES/32)   // 8128 (TRI_ % 32 == 0 -> one sample per batch)
#define EBLK  148
#define RBLK  96            // persistent recurrence CTAs (32 upd + 64 dec)

// ---------------- device scratch ----------------
__device__ __align__(16) float g_c0[D_];
__device__ __align__(16) float g_rnninp[M4*D_];
__device__ __align__(16) float g_ugi[M4*3*D_];
__device__ __align__(16) float g_mem[M4*D_];
__device__ __align__(16) float g_P[M4*D_];
__device__ __align__(16) float g_Q[M4*D_];
__device__ __align__(16) float g_hu[2][S_*D_];
__device__ __align__(16) float g_hd[2][S_*D_];
__device__ __align__(16) float g_part[EBLK*64];
__device__ int g_bar;

__device__ __forceinline__ float sigf(float x) { return 1.f/(1.f+expf(-x)); }

// ---------------- init ----------------
__global__ void k_init() {
    int i = blockIdx.x*blockDim.x + threadIdx.x;
    if (i < S_*D_) { g_hu[0][i] = 0.f; g_hd[0][i] = 0.f; }
    if (i == 0) g_bar = 0;
}

// ---------------- c0 = MLPReadout([z ; init]) ----------------
__global__ void k_c0(const float* __restrict__ z, const float* __restrict__ ip,
                     const float* __restrict__ W0, const float* __restrict__ b0,
                     const float* __restrict__ W1, const float* __restrict__ b1,
                     const float* __restrict__ W2, const float* __restrict__ b2)
{
    __shared__ float sin_[512];
    __shared__ float y0[256];
    __shared__ float y1[128];
    int tid = threadIdx.x;           // 256 threads
    sin_[tid]       = z[tid];
    sin_[256 + tid] = ip[tid];
    __syncthreads();
    float acc = b0[tid];
    for (int k = 0; k < 512; k++) acc += W0[tid*512 + k] * sin_[k];
    y0[tid] = fmaxf(acc, 0.f);
    __syncthreads();
    if (tid < 128) {
        float a = b1[tid];
        for (int k = 0; k < 256; k++) a += W1[tid*256 + k] * y0[k];
        y1[tid] = fmaxf(a, 0.f);
    }
    __syncthreads();
    float a2 = b2[tid];
    for (int k = 0; k < 128; k++) a2 += W2[tid*128 + k] * y1[k];
    g_c0[tid] = a2;
}

// ---------------- 128x128-tile GEMM, 8x8 microtile: C = op(A @ B^T + bias) ----
// rowMode=1 maps GEMM row m -> x row (m + m/127 + 1)   (i.e. x[:, 1:])
__global__ void __launch_bounds__(256, 2) k_gemm(
    const float* __restrict__ A, int lda, int rowMode,
    const float* __restrict__ B, int ldb,
    const float* __restrict__ bias,
    float* __restrict__ C, int ldc,
    int M, int N, int K, int doRelu)
{
    __shared__ __align__(16) float As[2][16][132];
    __shared__ __align__(16) float Bs[2][16][132];
    int tid = threadIdx.x;                 // 256
    int bm = blockIdx.y << 7, bn = blockIdx.x << 7;
    int tx = tid & 15, ty = tid >> 4;
    int lr = tid & 127;                    // load row within tile
    int lq = (tid >> 7) << 3;              // k-offset within tile: 0 or 8
    int am = bm + lr;
    long arow = -1;
    if (am < M) arow = rowMode ? (long)(am + am/NM1 + 1) : (long)am;
    long brow = (long)(bn + lr);           // N multiple of 128 -> always valid

    float acc[8][8];
#pragma unroll
    for (int i = 0; i < 8; i++)
#pragma unroll
        for (int j = 0; j < 8; j++) acc[i][j] = 0.f;

    int ktiles = (K + 15) >> 4;
    float4 pa[2], pb[2];

    // ---- fetch tile 0 into registers ----
    {
        int k0 = lq;
        if (k0 + 7 < K) {
            if (arow >= 0) {
                pa[0] = *(const float4*)(A + arow*lda + k0);
                pa[1] = *(const float4*)(A + arow*lda + k0 + 4);
            } else { pa[0] = pa[1] = make_float4(0.f,0.f,0.f,0.f); }
            pb[0] = *(const float4*)(B + brow*ldb + k0);
            pb[1] = *(const float4*)(B + brow*ldb + k0 + 4);
        } else {
            float* ap = (float*)pa; float* bp = (float*)pb;
#pragma unroll
            for (int i = 0; i < 8; i++) {
                int k = k0 + i;
                ap[i] = (arow >= 0 && k < K) ? A[arow*lda + k] : 0.f;
                bp[i] = (k < K) ? B[brow*ldb + k] : 0.f;
            }
        }
        float* ap = (float*)pa; float* bp = (float*)pb;
#pragma unroll
        for (int i = 0; i < 8; i++) {
            As[0][lq + i][lr] = ap[i];
            Bs[0][lq + i][lr] = bp[i];
        }
    }
    __syncthreads();

    for (int kt = 0; kt < ktiles; kt++) {
        int cur = kt & 1, nxt = cur ^ 1;
        bool have_next = (kt + 1 < ktiles);
        if (have_next) {
            int k0 = ((kt + 1) << 4) + lq;
            if (k0 + 7 < K) {
                if (arow >= 0) {
                    pa[0] = *(const float4*)(A + arow*lda + k0);
                    pa[1] = *(const float4*)(A + arow*lda + k0 + 4);
                } else { pa[0] = pa[1] = make_float4(0.f,0.f,0.f,0.f); }
                pb[0] = *(const float4*)(B + brow*ldb + k0);
                pb[1] = *(const float4*)(B + brow*ldb + k0 + 4);
            } else {
                float* ap = (float*)pa; float* bp = (float*)pb;
#pragma unroll
                for (int i = 0; i < 8; i++) {
                    int k = k0 + i;
                    ap[i] = (arow >= 0 && k < K) ? A[arow*lda + k] : 0.f;
                    bp[i] = (k < K) ? B[brow*ldb + k] : 0.f;
                }
            }
        }
#pragma unroll
        for (int k = 0; k < 16; k++) {
            float4 a0 = *(const float4*)&As[cur][k][ty << 2];
            float4 a1 = *(const float4*)&As[cur][k][64 + (ty << 2)];
            float4 b0 = *(const float4*)&Bs[cur][k][tx << 2];
            float4 b1 = *(const float4*)&Bs[cur][k][64 + (tx << 2)];
            float ar[8] = {a0.x,a0.y,a0.z,a0.w, a1.x,a1.y,a1.z,a1.w};
            float br[8] = {b0.x,b0.y,b0.z,b0.w, b1.x,b1.y,b1.z,b1.w};
#pragma unroll
            for (int i = 0; i < 8; i++)
#pragma unroll
                for (int j = 0; j < 8; j++) acc[i][j] += ar[i]*br[j];
        }
        if (have_next) {
            float* ap = (float*)pa; float* bp = (float*)pb;
#pragma unroll
            for (int i = 0; i < 8; i++) {
                As[nxt][lq + i][lr] = ap[i];
                Bs[nxt][lq + i][lr] = bp[i];
            }
            __syncthreads();
        }
    }

    // ---- epilogue ----
    int c0 = bn + (tx << 2);
    int c1 = bn + 64 + (tx << 2);
    float4 bia0 = make_float4(0.f,0.f,0.f,0.f), bia1 = bia0;
    if (bias) {
        bia0 = *(const float4*)(bias + c0);
        bia1 = *(const float4*)(bias + c1);
    }
#pragma unroll
    for (int i = 0; i < 8; i++) {
        int row = (i < 4) ? (bm + (ty << 2) + i) : (bm + 64 + (ty << 2) + i - 4);
        if (row >= M) continue;
        float4 v0, v1;
        v0.x = acc[i][0] + bia0.x; v0.y = acc[i][1] + bia0.y;
        v0.z = acc[i][2] + bia0.z; v0.w = acc[i][3] + bia0.w;
        v1.x = acc[i][4] + bia1.x; v1.y = acc[i][5] + bia1.y;
        v1.z = acc[i][6] + bia1.z; v1.w = acc[i][7] + bia1.w;
        if (doRelu) {
            v0.x = fmaxf(v0.x,0.f); v0.y = fmaxf(v0.y,0.f);
            v0.z = fmaxf(v0.z,0.f); v0.w = fmaxf(v0.w,0.f);
            v1.x = fmaxf(v1.x,0.f); v1.y = fmaxf(v1.y,0.f);
            v1.z = fmaxf(v1.z,0.f); v1.w = fmaxf(v1.w,0.f);
        }
        *(float4*)(C + (long)row*ldc + c0) = v0;
        *(float4*)(C + (long)row*ldc + c1) = v1;
    }
}

// ---------------- persistent coupled recurrence ----------------
__device__ __forceinline__ void gridbar(int target) {
    __syncthreads();
    if (threadIdx.x == 0) {
        __threadfence();
        atomicAdd(&g_bar, 1);
        volatile int* p = &g_bar;
        while (*p < target) { }
        __threadfence();
    }
    __syncthreads();
}

__global__ void __launch_bounds__(256, 2) k_recur(
    const float* __restrict__ uWhh, const float* __restrict__ ubhh,
    const float* __restrict__ dWih, const float* __restrict__ dbih,
    const float* __restrict__ dWhh, const float* __restrict__ dbhh)
{
    extern __shared__ __align__(16) float sm[];
    int tid = threadIdx.x;   // 256
    int b = blockIdx.x;

    if (b < 32) {
        int dbase = b << 3;
        float* sh = sm;          // 32 x 260
        float* sw = sm + 8320;   // 24 x 260
        {
            const float4* wsrc = (const float4*)uWhh;
            float4* sw4 = (float4*)sw;
#pragma unroll
            for (int i = 0; i < 6; i++) {
                int fi = tid + (i << 8);
                int rr = fi >> 6, k4 = fi & 63;
                int g = rr >> 3, dl = rr & 7;
                sw4[rr*65 + k4] = wsrc[(g*256 + dbase + dl)*64 + k4];
            }
        }
        int s = tid >> 3, dl = tid & 7;
        int d = dbase + dl;
        float bh0 = ubhh[d], bh1 = ubhh[256 + d], bh2 = ubhh[512 + d];
        const float4* w0 = (const float4*)sw + dl*65;
        const float4* w1 = w0 + 8*65;
        const float4* w2 = w0 + 16*65;
        for (int t = 0; t < NM1; t++) {
            int par = t & 1;
            {
                const float4* hsrc = (const float4*)g_hu[par];
                float4* sh4 = (float4*)sh;
#pragma unroll
                for (int i = 0; i < 8; i++) {
                    int fi = tid + (i << 8);
                    int r = fi >> 6, k4 = fi & 63;
                    sh4[r*65 + k4] = __ldcg(hsrc + fi);
                }
            }
            __syncthreads();
            const float4* hv = (const float4*)sh + s*65;
            float a0 = 0.f, a1 = 0.f, a2 = 0.f;
#pragma unroll 8
            for (int k = 0; k < 64; k++) {
                float4 h  = hv[k];
                float4 x0 = w0[k], x1 = w1[k], x2 = w2[k];
                a0 += h.x*x0.x + h.y*x0.y + h.z*x0.z + h.w*x0.w;
                a1 += h.x*x1.x + h.y*x1.y + h.z*x1.z + h.w*x1.w;
                a2 += h.x*x2.x + h.y*x2.y + h.z*x2.z + h.w*x2.w;
            }
            const float* gi = g_ugi + (long)(s*NM1 + t)*768;
            float r = sigf(gi[d]       + a0 + bh0);
            float z = sigf(gi[256 + d] + a1 + bh1);
            float n = tanhf(gi[512 + d] + r*(a2 + bh2));
            float ho = sh[s*260 + d];
            __stcg(&g_hu[par ^ 1][s*256 + d], (1.f - z)*n + z*ho);
            if (t < NM1-1) gridbar((t+1)*RBLK); else { __syncthreads(); }
        }
    } else {
        int b2 = b - 32;
        int dbase = b2 << 2;
        float* sinp = sm;             // 32 x 260
        float* shd  = sm + 8320;      // 32 x 260
        float* swi  = sm + 16640;     // 12 x 260
        float* swh  = sm + 19760;     // 12 x 260
        float* sx   = sm + 22880;     // 768
        {
            const float4* wi4 = (const float4*)dWih;
            const float4* wh4 = (const float4*)dWhh;
            float4* swi4 = (float4*)swi;
            float4* swh4 = (float4*)swh;
#pragma unroll
            for (int i = 0; i < 3; i++) {
                int fi = tid + (i << 8);
                int rr = fi >> 6, k4 = fi & 63;
                int g = rr >> 2, dl = rr & 3;
                swi4[rr*65 + k4] = wi4[(g*256 + dbase + dl)*64 + k4];
                swh4[rr*65 + k4] = wh4[(g*256 + dbase + dl)*64 + k4];
            }
        }
        int s = tid >> 3;
        int rem = tid & 7;
        int dl = rem >> 1;
        int which = rem & 1;   // 0: input gates, 1: hidden gates
        int d = dbase + dl;
        const float* bsrc = which ? dbhh : dbih;
        float bv0 = bsrc[d], bv1 = bsrc[256 + d], bv2 = bsrc[512 + d];
        const float4* wr0 = (const float4*)(which ? swh : swi) + dl*65;
        const float4* wr1 = wr0 + 4*65;
        const float4* wr2 = wr0 + 8*65;
        for (int t = 0; t < NM1; t++) {
            int par = t & 1;
            {
                float4* si4 = (float4*)sinp;
                float4* sd4 = (float4*)shd;
                const float4* hd4 = (const float4*)g_hd[par];
                if (t == 0) {
                    const float4* c04 = (const float4*)g_c0;
#pragma unroll
                    for (int i = 0; i < 8; i++) {
                        int fi = tid + (i << 8);
                        int r = fi >> 6, k4 = fi & 63;
                        si4[r*65 + k4] = c04[k4];
                        sd4[r*65 + k4] = __ldcg(hd4 + fi);
                    }
                } else {
                    const float4* hu4 = (const float4*)g_hu[par];
#pragma unroll
                    for (int i = 0; i < 8; i++) {
                        int fi = tid + (i << 8);
                        int r = fi >> 6, k4 = fi & 63;
                        si4[r*65 + k4] = __ldcg(hu4 + fi);
                        sd4[r*65 + k4] = __ldcg(hd4 + fi);
                    }
                }
            }
            __syncthreads();
            const float4* vec = (const float4*)(which ? shd : sinp) + s*65;
            float a0 = 0.f, a1 = 0.f, a2 = 0.f;
#pragma unroll 8
            for (int k = 0; k < 64; k++) {
                float4 h  = vec[k];
                float4 x0 = wr0[k], x1 = wr1[k], x2 = wr2[k];
                a0 += h.x*x0.x + h.y*x0.y + h.z*x0.z + h.w*x0.w;
                a1 += h.x*x1.x + h.y*x1.y + h.z*x1.z + h.w*x1.w;
                a2 += h.x*x2.x + h.y*x2.y + h.z*x2.z + h.w*x2.w;
            }
            int xb = (s*4 + dl)*6 + which;
            sx[xb + 0] = a0 + bv0;
            sx[xb + 2] = a1 + bv1;
            sx[xb + 4] = a2 + bv2;
            __syncthreads();
            if (which == 0) {
                int base = (s*4 + dl)*6;
                float r = sigf(sx[base+0] + sx[base+1]);
                float z = sigf(sx[base+2] + sx[base+3]);
                float n = tanhf(sx[base+4] + r*sx[base+5]);
                float ho = shd[s*260 + d];
                float hnew = (1.f - z)*n + z*ho;
                __stcg(&g_hd[par ^ 1][s*256 + d], hnew);
                g_mem[(long)(s*NM1 + t)*256 + d] = hnew;
            }
            if (t < NM1-1) gridbar((t+1)*RBLK); else { __syncthreads(); }
        }
    }
}

// ---------------- edge readout (tf32 WMMA) + BCE partial sums ----------------
// smem layout (floats):
#define EB_W1   0                       // 128 x 264 = 33792
#define EB_H0   33792                   // 32 x 264  = 8448
#define EB_H1   42240                   // 32 x 128  = 4096
#define EB_W2   46336                   // 256
#define EB_B1   46592                   // 128
#define EB_B2   46720                   // 4
#define EB_LOG  46724                   // 64
#define EB_ACC  46788                   // 64
#define EB_TMP  46852                   // 4
#define EB_IDX  46856                   // ints: RP 32 + RQ 32
#define EB_TOT  46920                   // floats -> 187680 B

__global__ void k_edge(const float* __restrict__ con,
                       const float* __restrict__ W1,
                       const float* __restrict__ b1,
                       const float* __restrict__ W2,
                       const float* __restrict__ b2)
{
    extern __shared__ __align__(16) float sm[];
    float* sW1  = sm + EB_W1;
    float* sh0  = sm + EB_H0;
    float* sh1  = sm + EB_H1;
    float* sW2  = sm + EB_W2;
    float* sb1  = sm + EB_B1;
    float* sb2v = sm + EB_B2;
    float* slog = sm + EB_LOG;
    float* sacc = sm + EB_ACC;
    float* stmp = sm + EB_TMP;
    int*   sRP  = (int*)(sm + EB_IDX);
    int*   sRQ  = sRP + 32;

    int tid = threadIdx.x; // 256
    {
        const float4* w4 = (const float4*)W1;
        float4* d4 = (float4*)sW1;
        for (int fi = tid; fi < 128*64; fi += 256) {
            int r = fi >> 6, k4 = fi & 63;
            d4[r*66 + k4] = w4[fi];          // stride 264 floats = 66 float4
        }
    }
    sW2[tid] = W2[tid];
    if (tid < 128) sb1[tid] = b1[tid];
    if (tid < 2)   sb2v[tid] = b2[tid];
    if (tid < 64)  sacc[tid] = 0.f;
    __syncthreads();

    const float4* P4 = (const float4*)g_P;
    const float4* Q4 = (const float4*)g_Q;

    int w  = tid >> 5;
    int mt = w & 1;                    // m-tile (rows 16*mt..)
    int nt0 = (w >> 1) << 1;           // first n-tile of this warp's pair

    for (int bb = blockIdx.x; bb < NBATCH; bb += gridDim.x) {
        int base = bb * 32;
        int s = base / TRI_;           // whole batch lies in one sample
        if (tid < 32) {
            int e = base + tid - s*TRI_;
            int i = (int)(0.5f*(sqrtf(8.f*(float)e + 1.f) - 1.f));
            while ((i+1)*(i+2)/2 <= e) ++i;
            while (i*(i+1)/2 > e)      --i;
            int j = e - i*(i+1)/2;
            sRP[tid] = (s*NM1 + j)*64;
            sRQ[tid] = (s*NM1 + i)*64;
        }
        __syncthreads();
        // h0 = relu(P_j + Q_i)  (32 x 256, stride 264)
        {
            float4* h04 = (float4*)sh0;
#pragma unroll
            for (int v = 0; v < 8; v++) {
                int fi = tid + (v << 8);
                int le = fi >> 6, k4 = fi & 63;
                float4 p = P4[sRP[le] + k4];
                float4 q = Q4[sRQ[le] + k4];
                float4 r;
                r.x = fmaxf(p.x + q.x, 0.f);
                r.y = fmaxf(p.y + q.y, 0.f);
                r.z = fmaxf(p.z + q.z, 0.f);
                r.w = fmaxf(p.w + q.w, 0.f);
                h04[le*66 + k4] = r;
            }
        }
        __syncthreads();
        // h1raw = h0 @ W1^T via tf32 WMMA (bias+relu applied in logit pass)
        {
            wmma::fragment<wmma::accumulator, 16,16,8, float> fc0, fc1;
            wmma::fill_fragment(fc0, 0.f);
            wmma::fill_fragment(fc1, 0.f);
            const float* aBase = sh0 + mt*16*264;
            const float* b0Base = sW1 + (nt0*16)*264;
            const float* b1Base = sW1 + ((nt0+1)*16)*264;
            for (int kt = 0; kt < 32; kt++) {
                wmma::fragment<wmma::matrix_a, 16,16,8, wmma::precision::tf32, wmma::row_major> fa;
                wmma::fragment<wmma::matrix_b, 16,16,8, wmma::precision::tf32, wmma::col_major> fb0, fb1;
                wmma::load_matrix_sync(fa,  aBase  + kt*8, 264);
                wmma::load_matrix_sync(fb0, b0Base + kt*8, 264);
                wmma::load_matrix_sync(fb1, b1Base + kt*8, 264);
#pragma unroll
                for (int t = 0; t < fa.num_elements; t++)  fa.x[t]  = wmma::__float_to_tf32(fa.x[t]);
#pragma unroll
                for (int t = 0; t < fb0.num_elements; t++) fb0.x[t] = wmma::__float_to_tf32(fb0.x[t]);
#pragma unroll
                for (int t = 0; t < fb1.num_elements; t++) fb1.x[t] = wmma::__float_to_tf32(fb1.x[t]);
                wmma::mma_sync(fc0, fa, fb0, fc0);
                wmma::mma_sync(fc1, fa, fb1, fc1);
            }
            wmma::store_matrix_sync(sh1 + mt*16*128 + nt0*16,     fc0, 128, wmma::mem_row_major);
            wmma::store_matrix_sync(sh1 + mt*16*128 + (nt0+1)*16, fc1, 128, wmma::mem_row_major);
        }
        __syncthreads();
        // logits (relu(h1raw + b1) dot W2)
        if (tid < 64) {
            int le = tid >> 1, cls = tid & 1;
            float l = sb2v[cls];
            const float* hh = sh1 + le*128;
            const float* ww = sW2 + cls*128;
#pragma unroll 4
            for (int k = 0; k < 128; k++) l += fmaxf(hh[k] + sb1[k], 0.f) * ww[k];
            slog[le*2 + cls] = l;
        }
        __syncthreads();
        // softmax + clamped BCE, then deterministic shuffle-tree reduction
        float v = 0.f;
        if (tid < 64) {
            int le = tid >> 1, cls = tid & 1;
            float l0 = slog[le*2], l1 = slog[le*2 + 1];
            float mx = fmaxf(l0, l1);
            float ex0 = expf(l0 - mx), ex1 = expf(l1 - mx);
            float inv = 1.f/(ex0 + ex1);
            float p = (cls ? ex1 : ex0) * inv;
            float lg = fmaxf(logf(p),     -100.f);
            float lm = fmaxf(log1pf(-p),  -100.f);
            float c = con[(long)(base + le)*2 + cls];
            v = -(c*lg + (1.f - c)*lm);
#pragma unroll
            for (int off = 2; off < 32; off <<= 1)
                v += __shfl_xor_sync(0xffffffffu, v, off);
            if ((tid & 31) < 2) stmp[(tid >> 5)*2 + (tid & 1)] = v;
        }
        __syncthreads();
        if (tid < 2) sacc[s*2 + tid] += stmp[tid] + stmp[2 + tid];
        __syncthreads();
    }
    if (tid < 64) g_part[blockIdx.x*64 + tid] = sacc[tid];
}

// ---------------- deterministic final reduction ----------------
__global__ void k_reduce(float* __restrict__ out) {
    int tid = threadIdx.x; // 64
    float a = 0.f;
    for (int b = 0; b < EBLK; b++) a += g_part[b*64 + tid];
    out[tid] = a;
}

extern "C" void kernel_launch(void* const* d_in, const int* in_sizes, int n_in,
                              void* d_out, int out_size) {
    const float* x       = (const float*)d_in[0];
    const float* con     = (const float*)d_in[1];
    const float* z_ph    = (const float*)d_in[2];
    const float* init_ph = (const float*)d_in[3];
    const float* cc_W0   = (const float*)d_in[4];
    const float* cc_b0   = (const float*)d_in[5];
    const float* cc_W1   = (const float*)d_in[6];
    const float* cc_b1   = (const float*)d_in[7];
    const float* cc_W2   = (const float*)d_in[8];
    const float* cc_b2   = (const float*)d_in[9];
    const float* er_W0   = (const float*)d_in[10];
    const float* er_b0   = (const float*)d_in[11];
    const float* er_W1   = (const float*)d_in[12];
    const float* er_b1   = (const float*)d_in[13];
    const float* er_W2   = (const float*)d_in[14];
    const float* er_b2   = (const float*)d_in[15];
    const float* rr_W    = (const float*)d_in[16];
    const float* rr_b    = (const float*)d_in[17];
    const float* dec_Wih = (const float*)d_in[18];
    const float* dec_Whh = (const float*)d_in[19];
    const float* dec_bih = (const float*)d_in[20];
    const float* dec_bhh = (const float*)d_in[21];
    const float* upd_Wih = (const float*)d_in[22];
    const float* upd_Whh = (const float*)d_in[23];
    const float* upd_bih = (const float*)d_in[24];
    const float* upd_bhh = (const float*)d_in[25];
    float* out = (float*)d_out;

    cudaFuncSetAttribute(k_recur, cudaFuncAttributeMaxDynamicSharedMemorySize, 23648*4);
    cudaFuncSetAttribute(k_edge,  cudaFuncAttributeMaxDynamicSharedMemorySize, EB_TOT*4);

    k_init<<<32, 256>>>();
    k_c0<<<1, 256>>>(z_ph, init_ph, cc_W0, cc_b0, cc_W1, cc_b1, cc_W2, cc_b2);
    // rnninp = relu(x[:,1:] @ rr_W^T + rr_b)   (M=4064, N=256, K=516)
    k_gemm<<<dim3(2, 32), 256>>>(x, F_, 1, rr_W, F_, rr_b, g_rnninp, D_,
                                 M4, D_, F_, 1);
    // ugi = rnninp @ upd_Wih^T + upd_bih       (M=4064, N=768, K=256)
    k_gemm<<<dim3(6, 32), 256>>>(g_rnninp, D_, 0, upd_Wih, D_, upd_bih, g_ugi, 3*D_,
                                 M4, 3*D_, D_, 0);
    // persistent coupled recurrence (127 steps, 1 launch)
    k_recur<<<RBLK, 256, 23648*4>>>(upd_Whh, upd_bhh,
                                    dec_Wih, dec_bih, dec_Whh, dec_bhh);
    // P = mem @ W0a^T ; Q = mem @ W0b^T + b0   (er_W0 is (256, 512))
    k_gemm<<<dim3(2, 32), 256>>>(g_mem, D_, 0, er_W0, 2*D_, nullptr, g_P, D_,
                                 M4, D_, D_, 0);
    k_gemm<<<dim3(2, 32), 256>>>(g_mem, D_, 0, er_W0 + D_, 2*D_, er_b0, g_Q, D_,
                                 M4, D_, D_, 0);
    // edge MLP + BCE
    k_edge<<<EBLK, 256, EB_TOT*4>>>(con, er_W1, er_b1, er_W2, er_b2);
    k_reduce<<<1, 64>>>(out);
}